// round 2
// baseline (speedup 1.0000x reference)
#include <cuda_runtime.h>
#include <math.h>

#define N_NODES   8192
#define K_NBR     64
#define TWO_N     (2 * N_NODES)
#define BN_EPS    1e-3f

// Split-K GEMV config
#define COL_TILES   8          // 8192 cols / 1024 cols-per-block
#define ROW_CHUNKS  64         // 16384 rows / 256 rows-per-chunk
#define ROWS_PER_CHUNK (TWO_N / ROW_CHUNKS)   // 256
#define THREADS_B   256        // each thread owns 4 cols (float4)

// scratch (no allocation allowed in kernel_launch)
__device__ float g_h[TWO_N];
__device__ float g_part[ROW_CHUNKS * N_NODES];

// ---------------------------------------------------------------------------
// K1: gather neighbors, sum, BN, build h = concat(BN(x), BN(x + ngh_sum))
// One warp per node. adj is int32 (JAX x64 disabled downcasts int64->int32).
// ---------------------------------------------------------------------------
__global__ void build_h_kernel(const float* __restrict__ x,
                               const int* __restrict__ adj,
                               const float* __restrict__ gamma,
                               const float* __restrict__ beta,
                               const float* __restrict__ mean,
                               const float* __restrict__ var)
{
    const int warpId = threadIdx.x >> 5;
    const int lane   = threadIdx.x & 31;
    const int node   = blockIdx.x * (blockDim.x >> 5) + warpId;
    if (node >= N_NODES) return;

    const int* arow = adj + node * K_NBR;
    int a0 = arow[lane];
    int a1 = arow[lane + 32];
    float s = __ldg(&x[a0]) + __ldg(&x[a1]);

    #pragma unroll
    for (int off = 16; off > 0; off >>= 1)
        s += __shfl_down_sync(0xffffffffu, s, off);

    if (lane == 0) {
        float xv = x[node];
        // BN for h[node] (the raw x part)
        {
            float inv = rsqrtf(var[node] + BN_EPS);
            g_h[node] = (xv - mean[node]) * inv * gamma[node] + beta[node];
        }
        // BN for h[N + node] (the agg = x + ngh_sum part)
        {
            int j = N_NODES + node;
            float agg = xv + s;
            float inv = rsqrtf(var[j] + BN_EPS);
            g_h[j] = (agg - mean[j]) * inv * gamma[j] + beta[j];
        }
    }
}

// ---------------------------------------------------------------------------
// K2: split-K GEMV partials.
// grid = (COL_TILES, ROW_CHUNKS). Block caches its 256 h values in smem,
// each thread streams a float4 column slice of W (coalesced 128B loads).
// partial[chunk][col] is written exactly once -> deterministic.
// ---------------------------------------------------------------------------
__global__ __launch_bounds__(THREADS_B)
void gemv_partial_kernel(const float* __restrict__ W)
{
    __shared__ float sh[ROWS_PER_CHUNK];

    const int colBase = blockIdx.x * (THREADS_B * 4) + threadIdx.x * 4;
    const int rowBase = blockIdx.y * ROWS_PER_CHUNK;

    // load h chunk into smem
    sh[threadIdx.x] = g_h[rowBase + threadIdx.x];
    __syncthreads();

    float4 acc = make_float4(0.f, 0.f, 0.f, 0.f);
    const float* wp = W + (long long)rowBase * N_NODES + colBase;

    #pragma unroll 8
    for (int r = 0; r < ROWS_PER_CHUNK; ++r) {
        float hv = sh[r];
        float4 w = *reinterpret_cast<const float4*>(wp);
        acc.x = fmaf(hv, w.x, acc.x);
        acc.y = fmaf(hv, w.y, acc.y);
        acc.z = fmaf(hv, w.z, acc.z);
        acc.w = fmaf(hv, w.w, acc.w);
        wp += N_NODES;
    }

    *reinterpret_cast<float4*>(&g_part[(long long)blockIdx.y * N_NODES + colBase]) = acc;
}

// ---------------------------------------------------------------------------
// K3: reduce partials, add bias, exact-erf gelu, write output.
// ---------------------------------------------------------------------------
__global__ void reduce_gelu_kernel(const float* __restrict__ bias,
                                   float* __restrict__ out)
{
    const int j = blockIdx.x * blockDim.x + threadIdx.x;
    if (j >= N_NODES) return;

    float s = 0.f;
    #pragma unroll
    for (int c = 0; c < ROW_CHUNKS; ++c)
        s += g_part[c * N_NODES + j];

    float z = s + bias[j];
    // exact gelu: 0.5 * z * (1 + erf(z / sqrt(2)))
    out[j] = 0.5f * z * (1.0f + erff(z * 0.70710678118654752440f));
}

// ---------------------------------------------------------------------------
extern "C" void kernel_launch(void* const* d_in, const int* in_sizes, int n_in,
                              void* d_out, int out_size)
{
    const float* x     = (const float*)d_in[0];  // input_data [1,N]
    const int*   adj   = (const int*)d_in[1];    // adj [N,K] int32 (JAX x64 off)
    // d_in[2] = edge_weights (unused by reference)
    const float* W     = (const float*)d_in[3];  // [2N, N]
    const float* b     = (const float*)d_in[4];  // [N]
    const float* gamma = (const float*)d_in[5];  // [2N]
    const float* beta  = (const float*)d_in[6];  // [2N]
    const float* mean  = (const float*)d_in[7];  // [2N]
    const float* var   = (const float*)d_in[8];  // [2N]
    float*       out   = (float*)d_out;

    // K1: 8 warps per block -> 1024 blocks of 256 threads
    build_h_kernel<<<N_NODES / 8, 256>>>(x, adj, gamma, beta, mean, var);

    // K2: split-K GEMV
    dim3 grid2(COL_TILES, ROW_CHUNKS);
    gemv_partial_kernel<<<grid2, THREADS_B>>>(W);

    // K3: epilogue
    reduce_gelu_kernel<<<(N_NODES + 255) / 256, 256>>>(b, out);
}